// round 1
// baseline (speedup 1.0000x reference)
#include <cuda_runtime.h>
#include <cuda_bf16.h>
#include <cstdint>

// ---------------------------------------------------------------------------
// ROIAlignPooler (3D, 4-level FPN) for B200 (sm_100a)
//
// Strategy:
//   1. Transpose each feature level NCDHW -> N DHW C (channel-contiguous)
//      into static __device__ scratch.  One trilinear tap then serves all 64
//      channels with a single coalesced 256B warp load (lanes = channels,
//      float2 each).
//   2. One block per ROI (256 blocks, 512 threads = 16 warps).  Each warp
//      owns output cells (7x7x7 = 343) round-robin.  Per cell: 4 taps/dim
//      (2 supersamples x 2 corners), fully unrolled 4x4x4 = 64 taps.
//   3. Results staged in shared memory [C][343], then written coalesced.
// ---------------------------------------------------------------------------

#define NB      128      // rois per batch image
#define NROI    256      // total rois (B=2)
#define C_CH    64
#define CELLS   343      // 7*7*7
#define OUT_PER_ROI (C_CH * CELLS)

// Transposed feature scratch (channel-last). Total ~37.4 MB.
__device__ float g_t0[2 * 40 * 40 * 40 * C_CH];
__device__ float g_t1[2 * 20 * 20 * 20 * C_CH];
__device__ float g_t2[2 * 10 * 10 * 10 * C_CH];
__device__ float g_t3[2 * 5 * 5 * 5 * C_CH];

// ---------------------------------------------------------------------------
// Tiled transpose: src[b][c][sp] -> dst[b][sp][c]   (C = 64, B = 2)
// ---------------------------------------------------------------------------
__global__ void transpose_kernel(const float* __restrict__ src, int lvl, int Dsz) {
    float* dst = (lvl == 0) ? g_t0 : (lvl == 1) ? g_t1 : (lvl == 2) ? g_t2 : g_t3;
    const int DHW = Dsz * Dsz * Dsz;
    __shared__ float tile[32][33];
    const int b     = blockIdx.z;
    const int cBase = blockIdx.y * 32;
    const int sBase = blockIdx.x * 32;
    const int tx = threadIdx.x, ty = threadIdx.y;

    int sp = sBase + tx;
    if (sp < DHW)
        tile[ty][tx] = src[(size_t)(b * C_CH + cBase + ty) * DHW + sp];
    __syncthreads();
    int sp2 = sBase + ty;
    if (sp2 < DHW)
        dst[((size_t)b * DHW + sp2) * C_CH + cBase + tx] = tile[tx][ty];
}

// ---------------------------------------------------------------------------
// Per-dim tap computation.  Produces 4 (offset, weight) pairs:
//   2 supersamples (r=0,1) x 2 corners (low, high).
// Weight already includes the 0.5 averaging factor for this dim
// (0.5^3 across three dims = 1/8 mean over the 2x2x2 supersamples).
// Offsets are pre-multiplied by the element stride of this dim.
// ---------------------------------------------------------------------------
__device__ __forceinline__ void dim_taps(float start, float bin, int o, int Dsz,
                                         int stride, int* to, float* tw) {
#pragma unroll
    for (int r = 0; r < 2; r++) {
        float c = start + ((float)(2 * o + r) + 0.5f) * 0.5f * bin;
        float valid = (c > -1.0f && c < (float)Dsz) ? 0.5f : 0.0f;
        c = fminf(fmaxf(c, 0.0f), (float)Dsz - 1.0f);
        float low = floorf(c);
        int li = (int)low;
        int hi = min(li + 1, Dsz - 1);
        float f = c - low;
        to[2 * r]     = li * stride;
        tw[2 * r]     = (1.0f - f) * valid;
        to[2 * r + 1] = hi * stride;
        tw[2 * r + 1] = f * valid;
    }
}

// ---------------------------------------------------------------------------
// Main kernel: one block per ROI.
// ---------------------------------------------------------------------------
extern __shared__ float s_out[];   // [C_CH][CELLS] = 87808 bytes

__global__ __launch_bounds__(512, 2)
void roi_align_kernel(const float* __restrict__ boxes, float* __restrict__ out) {
    const int r = blockIdx.x;          // roi index 0..255
    const int b = r >> 7;              // batch image (nb = 128)

    // ---- box, level selection (uniform across block) ----
    const float bz1 = boxes[r * 6 + 0];
    const float by1 = boxes[r * 6 + 1];
    const float bx1 = boxes[r * 6 + 2];
    const float bz2 = boxes[r * 6 + 3];
    const float by2 = boxes[r * 6 + 4];
    const float bx2 = boxes[r * 6 + 5];

    const float area = (bz2 - bz1 + 1.0f) * (by2 - by1 + 1.0f) * (bx2 - bx1 + 1.0f);
    const float s    = sqrtf(area);
    float lf = floorf(4.0f + log2f(s / 224.0f + 1e-6f));
    lf = fminf(fmaxf(lf, 2.0f), 5.0f);
    const int lvl = (int)lf - 2;

    const float* ft;
    int Dsz;
    float scale;
    if (lvl == 0)      { ft = g_t0; Dsz = 40; scale = 0.25f;    }
    else if (lvl == 1) { ft = g_t1; Dsz = 20; scale = 0.125f;   }
    else if (lvl == 2) { ft = g_t2; Dsz = 10; scale = 0.0625f;  }
    else               { ft = g_t3; Dsz = 5;  scale = 0.03125f; }

    const int DHW = Dsz * Dsz * Dsz;
    const int strideZ = Dsz * Dsz * C_CH;
    const int strideY = Dsz * C_CH;
    const int strideX = C_CH;

    const float z1 = bz1 * scale, y1 = by1 * scale, x1 = bx1 * scale;
    const float z2 = bz2 * scale, y2 = by2 * scale, x2 = bx2 * scale;
    const float binz = fmaxf(z2 - z1, 1.0f) * (1.0f / 7.0f);
    const float biny = fmaxf(y2 - y1, 1.0f) * (1.0f / 7.0f);
    const float binx = fmaxf(x2 - x1, 1.0f) * (1.0f / 7.0f);

    const int lane = threadIdx.x & 31;
    const int warp = threadIdx.x >> 5;

    // each lane handles channels (2*lane, 2*lane+1) — float2, 8B aligned
    const float* base = ft + (size_t)b * DHW * C_CH + 2 * lane;

    for (int cell = warp; cell < CELLS; cell += 16) {
        const int oz  = cell / 49;
        const int rem = cell - oz * 49;
        const int oy  = rem / 7;
        const int ox  = rem - oy * 7;

        int zo[4], yo[4], xo[4];
        float zw[4], yw[4], xw[4];
        dim_taps(z1, binz, oz, Dsz, strideZ, zo, zw);
        dim_taps(y1, biny, oy, Dsz, strideY, yo, yw);
        dim_taps(x1, binx, ox, Dsz, strideX, xo, xw);

        float accx = 0.0f, accy = 0.0f;
#pragma unroll
        for (int i = 0; i < 4; i++) {
#pragma unroll
            for (int j = 0; j < 4; j++) {
                const float wzy = zw[i] * yw[j];
                const int   ozy = zo[i] + yo[j];
#pragma unroll
                for (int k = 0; k < 4; k++) {
                    const float w = wzy * xw[k];
                    const float2 v = *(const float2*)(base + ozy + xo[k]);
                    accx = fmaf(w, v.x, accx);
                    accy = fmaf(w, v.y, accy);
                }
            }
        }

        s_out[(2 * lane)     * CELLS + cell] = accx;
        s_out[(2 * lane + 1) * CELLS + cell] = accy;
    }

    __syncthreads();

    // coalesced write-out: out[r][c][cell], s_out layout is [c][cell]
    float* o = out + (size_t)r * OUT_PER_ROI;
    for (int i = threadIdx.x; i < OUT_PER_ROI; i += 512)
        o[i] = s_out[i];
}

// ---------------------------------------------------------------------------
extern "C" void kernel_launch(void* const* d_in, const int* in_sizes, int n_in,
                              void* d_out, int out_size) {
    const float* x0    = (const float*)d_in[0];
    const float* x1    = (const float*)d_in[1];
    const float* x2    = (const float*)d_in[2];
    const float* x3    = (const float*)d_in[3];
    const float* boxes = (const float*)d_in[4];

    // 87808 B dynamic smem > 48KB default: opt in (idempotent; also runs on
    // the non-captured correctness call, so the attribute is set before capture)
    cudaFuncSetAttribute(roi_align_kernel,
                         cudaFuncAttributeMaxDynamicSharedMemorySize,
                         OUT_PER_ROI * (int)sizeof(float));

    dim3 tb(32, 32);
    transpose_kernel<<<dim3(2000, 2, 2), tb>>>(x0, 0, 40);
    transpose_kernel<<<dim3(250,  2, 2), tb>>>(x1, 1, 20);
    transpose_kernel<<<dim3(32,   2, 2), tb>>>(x2, 2, 10);
    transpose_kernel<<<dim3(4,    2, 2), tb>>>(x3, 3, 5);

    roi_align_kernel<<<NROI, 512, OUT_PER_ROI * (int)sizeof(float)>>>(
        boxes, (float*)d_out);
}

// round 2
// speedup vs baseline: 1.7046x; 1.7046x over previous
#include <cuda_runtime.h>
#include <cuda_bf16.h>
#include <cstdint>

// ---------------------------------------------------------------------------
// ROIAlignPooler (3D, 4-level FPN) for B200 (sm_100a)
//
//   1. Single fused transpose kernel: all 4 levels NCDHW -> N DHW C into
//      static __device__ scratch (channel-last). One trilinear tap then
//      serves 64 channels coalesced.
//   2. Main kernel: one block per ROI (256 blocks, 512 thr). Each warp
//      processes TWO cells at once: lane = (cell half, channel quad),
//      float4 per lane => one LDG.128 warp instr covers one 64-ch tap.
//   3. Output staged in shared [C][343], float4 coalesced writeout.
// ---------------------------------------------------------------------------

#define NROI    256
#define C_CH    64
#define CELLS   343
#define OUT_PER_ROI (C_CH * CELLS)   // 21952

__device__ __align__(16) float g_t0[2 * 40 * 40 * 40 * C_CH];
__device__ __align__(16) float g_t1[2 * 20 * 20 * 20 * C_CH];
__device__ __align__(16) float g_t2[2 * 10 * 10 * 10 * C_CH];
__device__ __align__(16) float g_t3[2 * 5 * 5 * 5 * C_CH];

// ---------------------------------------------------------------------------
// Fused transpose: src[b][c][sp] -> dst[b][sp][c] for all levels, one launch.
// Block = (32,32). Each block handles a 32-channel x 128-spatial tile (16KB).
// Block ranges: L0 [0,2000) L1 [2000,2252) L2 [2252,2284) L3 [2284,2288)
// ---------------------------------------------------------------------------
__global__ __launch_bounds__(1024)
void transpose_all_kernel(const float* __restrict__ x0,
                          const float* __restrict__ x1,
                          const float* __restrict__ x2,
                          const float* __restrict__ x3) {
    __shared__ float tile[32][133];   // pad 5 mod 32 -> conflict-free transpose

    const int bx = blockIdx.x;
    const float* src; float* dst; int DHW, spTiles, t0;
    if (bx < 2000)      { src = x0; dst = g_t0; DHW = 64000; spTiles = 500; t0 = bx; }
    else if (bx < 2252) { src = x1; dst = g_t1; DHW = 8000;  spTiles = 63;  t0 = bx - 2000; }
    else if (bx < 2284) { src = x2; dst = g_t2; DHW = 1000;  spTiles = 8;   t0 = bx - 2252; }
    else                { src = x3; dst = g_t3; DHW = 125;   spTiles = 1;   t0 = bx - 2284; }

    const int st = t0 % spTiles;
    const int t1 = t0 / spTiles;
    const int cg = t1 & 1;           // channel group (0/1)
    const int b  = t1 >> 1;          // batch image
    const int cBase = cg * 32;
    const int sBase = st * 128;

    const int tx = threadIdx.x, ty = threadIdx.y;

#pragma unroll
    for (int k = 0; k < 4; k++) {
        int sp = sBase + 32 * k + tx;
        if (sp < DHW)
            tile[ty][32 * k + tx] =
                src[(size_t)(b * C_CH + cBase + ty) * DHW + sp];
    }
    __syncthreads();
#pragma unroll
    for (int k = 0; k < 4; k++) {
        int sp = sBase + 32 * k + ty;
        if (sp < DHW)
            dst[((size_t)b * DHW + sp) * C_CH + cBase + tx] = tile[tx][32 * k + ty];
    }
}

// ---------------------------------------------------------------------------
// Per-dim taps: 2 supersamples x 2 corners = 4 (offset, weight) pairs.
// Weight includes the 0.5 per-dim averaging factor; offsets pre-scaled by
// the dim's element stride.
// ---------------------------------------------------------------------------
__device__ __forceinline__ void dim_taps(float start, float bin, int o, int Dsz,
                                         int stride, int* to, float* tw) {
#pragma unroll
    for (int r = 0; r < 2; r++) {
        float c = start + ((float)(2 * o + r) + 0.5f) * 0.5f * bin;
        float valid = (c > -1.0f && c < (float)Dsz) ? 0.5f : 0.0f;
        c = fminf(fmaxf(c, 0.0f), (float)Dsz - 1.0f);
        float low = floorf(c);
        int li = (int)low;
        int hi = min(li + 1, Dsz - 1);
        float f = c - low;
        to[2 * r]     = li * stride;
        tw[2 * r]     = (1.0f - f) * valid;
        to[2 * r + 1] = hi * stride;
        tw[2 * r + 1] = f * valid;
    }
}

// ---------------------------------------------------------------------------
// Main kernel: one block per ROI, 512 threads = 16 warps.
// Warp handles 2 cells per iteration: lane>>4 = cell half, lane&15 = ch quad.
// ---------------------------------------------------------------------------
extern __shared__ float s_out[];   // [C_CH][CELLS] = 87808 bytes

__global__ __launch_bounds__(512, 2)
void roi_align_kernel(const float* __restrict__ boxes, float* __restrict__ out) {
    const int r = blockIdx.x;
    const int b = r >> 7;            // nb = 128

    const float bz1 = boxes[r * 6 + 0];
    const float by1 = boxes[r * 6 + 1];
    const float bx1 = boxes[r * 6 + 2];
    const float bz2 = boxes[r * 6 + 3];
    const float by2 = boxes[r * 6 + 4];
    const float bx2 = boxes[r * 6 + 5];

    const float area = (bz2 - bz1 + 1.0f) * (by2 - by1 + 1.0f) * (bx2 - bx1 + 1.0f);
    const float s    = sqrtf(area);
    float lf = floorf(4.0f + log2f(s / 224.0f + 1e-6f));
    lf = fminf(fmaxf(lf, 2.0f), 5.0f);
    const int lvl = (int)lf - 2;

    const float* ft; int Dsz; float scale;
    if (lvl == 0)      { ft = g_t0; Dsz = 40; scale = 0.25f;    }
    else if (lvl == 1) { ft = g_t1; Dsz = 20; scale = 0.125f;   }
    else if (lvl == 2) { ft = g_t2; Dsz = 10; scale = 0.0625f;  }
    else               { ft = g_t3; Dsz = 5;  scale = 0.03125f; }

    const int DHW = Dsz * Dsz * Dsz;
    const int strideZ = Dsz * Dsz * C_CH;
    const int strideY = Dsz * C_CH;

    const float z1 = bz1 * scale, y1 = by1 * scale, x1 = bx1 * scale;
    const float binz = fmaxf(bz2 * scale - z1, 1.0f) * (1.0f / 7.0f);
    const float biny = fmaxf(by2 * scale - y1, 1.0f) * (1.0f / 7.0f);
    const float binx = fmaxf(bx2 * scale - x1, 1.0f) * (1.0f / 7.0f);

    const int lane = threadIdx.x & 31;
    const int warp = threadIdx.x >> 5;
    const int h = lane >> 4;         // cell half (0/1)
    const int q = lane & 15;         // channel quad -> channels 4q..4q+3

    const float* base = ft + (size_t)b * DHW * C_CH + 4 * q;

    for (int cb = 2 * warp; cb < CELLS; cb += 32) {
        const int cell = cb + h;
        const int cc   = min(cell, CELLS - 1);
        const int oz   = cc / 49;
        const int rem  = cc - oz * 49;
        const int oy   = rem / 7;
        const int ox   = rem - oy * 7;

        int zo[4], yo[4], xo[4];
        float zw[4], yw[4], xw[4];
        dim_taps(z1, binz, oz, Dsz, strideZ, zo, zw);
        dim_taps(y1, biny, oy, Dsz, strideY, yo, yw);
        dim_taps(x1, binx, ox, Dsz, C_CH,    xo, xw);

        float a0 = 0.f, a1 = 0.f, a2 = 0.f, a3 = 0.f;
#pragma unroll
        for (int i = 0; i < 4; i++) {
#pragma unroll
            for (int j = 0; j < 4; j++) {
                const float wzy = zw[i] * yw[j];
                const int   ozy = zo[i] + yo[j];
#pragma unroll
                for (int k = 0; k < 4; k++) {
                    const float w  = wzy * xw[k];
                    const float4 v = *(const float4*)(base + ozy + xo[k]);
                    a0 = fmaf(w, v.x, a0);
                    a1 = fmaf(w, v.y, a1);
                    a2 = fmaf(w, v.z, a2);
                    a3 = fmaf(w, v.w, a3);
                }
            }
        }

        if (cell < CELLS) {
            s_out[(4 * q + 0) * CELLS + cell] = a0;
            s_out[(4 * q + 1) * CELLS + cell] = a1;
            s_out[(4 * q + 2) * CELLS + cell] = a2;
            s_out[(4 * q + 3) * CELLS + cell] = a3;
        }
    }

    __syncthreads();

    float4*       o4 = (float4*)(out + (size_t)r * OUT_PER_ROI);
    const float4* s4 = (const float4*)s_out;
#pragma unroll 4
    for (int i = threadIdx.x; i < OUT_PER_ROI / 4; i += 512)
        o4[i] = s4[i];
}

// ---------------------------------------------------------------------------
extern "C" void kernel_launch(void* const* d_in, const int* in_sizes, int n_in,
                              void* d_out, int out_size) {
    const float* x0    = (const float*)d_in[0];
    const float* x1    = (const float*)d_in[1];
    const float* x2    = (const float*)d_in[2];
    const float* x3    = (const float*)d_in[3];
    const float* boxes = (const float*)d_in[4];

    cudaFuncSetAttribute(roi_align_kernel,
                         cudaFuncAttributeMaxDynamicSharedMemorySize,
                         OUT_PER_ROI * (int)sizeof(float));

    transpose_all_kernel<<<2288, dim3(32, 32)>>>(x0, x1, x2, x3);

    roi_align_kernel<<<NROI, 512, OUT_PER_ROI * (int)sizeof(float)>>>(
        boxes, (float*)d_out);
}

// round 3
// speedup vs baseline: 2.1179x; 1.2424x over previous
#include <cuda_runtime.h>
#include <cuda_bf16.h>
#include <cstdint>

// ---------------------------------------------------------------------------
// ROIAlignPooler (3D, 4-level FPN) for B200 (sm_100a)
//
//   1. Fused transpose: all 4 levels NCDHW -> N DHW C (channel-last scratch).
//   2. Main kernel: one block per ROI (256 blocks, 768 thr, single wave).
//      Per-ROI tap tables (21 of them) are computed ONCE into shared memory
//      with duplicate-coordinate merging: the 4 taps/dim (2 supersamples x
//      2 corners) collapse to the unique integer coords (typically 2) with
//      summed weights. Per cell the 4x4x4=64 loads become nz*ny*nx (~8).
//   3. Warp handles 2 cells: lane = (cell half, channel quad), float4/lane.
//   4. Output staged in shared [C][343], float4 coalesced writeout.
// ---------------------------------------------------------------------------

#define NROI    256
#define C_CH    64
#define CELLS   343
#define OUT_PER_ROI (C_CH * CELLS)   // 21952

__device__ __align__(16) float g_t0[2 * 40 * 40 * 40 * C_CH];
__device__ __align__(16) float g_t1[2 * 20 * 20 * 20 * C_CH];
__device__ __align__(16) float g_t2[2 * 10 * 10 * 10 * C_CH];
__device__ __align__(16) float g_t3[2 * 5 * 5 * 5 * C_CH];

// ---------------------------------------------------------------------------
// Fused transpose: src[b][c][sp] -> dst[b][sp][c], all levels in one launch.
// ---------------------------------------------------------------------------
__global__ __launch_bounds__(1024)
void transpose_all_kernel(const float* __restrict__ x0,
                          const float* __restrict__ x1,
                          const float* __restrict__ x2,
                          const float* __restrict__ x3) {
    __shared__ float tile[32][133];

    const int bx = blockIdx.x;
    const float* src; float* dst; int DHW, spTiles, t0;
    if (bx < 2000)      { src = x0; dst = g_t0; DHW = 64000; spTiles = 500; t0 = bx; }
    else if (bx < 2252) { src = x1; dst = g_t1; DHW = 8000;  spTiles = 63;  t0 = bx - 2000; }
    else if (bx < 2284) { src = x2; dst = g_t2; DHW = 1000;  spTiles = 8;   t0 = bx - 2252; }
    else                { src = x3; dst = g_t3; DHW = 125;   spTiles = 1;   t0 = bx - 2284; }

    const int st = t0 % spTiles;
    const int t1 = t0 / spTiles;
    const int cg = t1 & 1;
    const int b  = t1 >> 1;
    const int cBase = cg * 32;
    const int sBase = st * 128;
    const int tx = threadIdx.x, ty = threadIdx.y;

#pragma unroll
    for (int k = 0; k < 4; k++) {
        int sp = sBase + 32 * k + tx;
        if (sp < DHW)
            tile[ty][32 * k + tx] =
                src[(size_t)(b * C_CH + cBase + ty) * DHW + sp];
    }
    __syncthreads();
#pragma unroll
    for (int k = 0; k < 4; k++) {
        int sp = sBase + 32 * k + ty;
        if (sp < DHW)
            dst[((size_t)b * DHW + sp) * C_CH + cBase + tx] = tile[tx][32 * k + ty];
    }
}

// ---------------------------------------------------------------------------
// Per-dim taps: 2 supersamples x 2 corners. Weight includes the 0.5 per-dim
// averaging factor; offsets pre-scaled by the dim's element stride.
// ---------------------------------------------------------------------------
__device__ __forceinline__ void dim_taps(float start, float bin, int o, int Dsz,
                                         int stride, int* to, float* tw) {
#pragma unroll
    for (int r = 0; r < 2; r++) {
        float c = start + ((float)(2 * o + r) + 0.5f) * 0.5f * bin;
        float valid = (c > -1.0f && c < (float)Dsz) ? 0.5f : 0.0f;
        c = fminf(fmaxf(c, 0.0f), (float)Dsz - 1.0f);
        float low = floorf(c);
        int li = (int)low;
        int hi = min(li + 1, Dsz - 1);
        float f = c - low;
        to[2 * r]     = li * stride;
        tw[2 * r]     = (1.0f - f) * valid;
        to[2 * r + 1] = hi * stride;
        tw[2 * r + 1] = f * valid;
    }
}

// ---------------------------------------------------------------------------
// Main kernel: one block per ROI, 768 threads = 24 warps, 2 blocks/SM.
// ---------------------------------------------------------------------------
extern __shared__ float s_out[];   // [C_CH][CELLS] = 87808 bytes (dynamic)

__global__ __launch_bounds__(768, 2)
void roi_align_kernel(const float* __restrict__ boxes, float* __restrict__ out) {
    __shared__ int   s_cnt[3][7];
    __shared__ int   s_off[3][7][4];
    __shared__ float s_wt [3][7][4];

    const int r = blockIdx.x;
    const int b = r >> 7;            // nb = 128

    const float bz1 = boxes[r * 6 + 0];
    const float by1 = boxes[r * 6 + 1];
    const float bx1 = boxes[r * 6 + 2];
    const float bz2 = boxes[r * 6 + 3];
    const float by2 = boxes[r * 6 + 4];
    const float bx2 = boxes[r * 6 + 5];

    const float area = (bz2 - bz1 + 1.0f) * (by2 - by1 + 1.0f) * (bx2 - bx1 + 1.0f);
    const float s    = sqrtf(area);
    float lf = floorf(4.0f + log2f(s / 224.0f + 1e-6f));
    lf = fminf(fmaxf(lf, 2.0f), 5.0f);
    const int lvl = (int)lf - 2;

    const float* ft; int Dsz; float scale;
    if (lvl == 0)      { ft = g_t0; Dsz = 40; scale = 0.25f;    }
    else if (lvl == 1) { ft = g_t1; Dsz = 20; scale = 0.125f;   }
    else if (lvl == 2) { ft = g_t2; Dsz = 10; scale = 0.0625f;  }
    else               { ft = g_t3; Dsz = 5;  scale = 0.03125f; }

    const int DHW     = Dsz * Dsz * Dsz;
    const int strideZ = Dsz * Dsz * C_CH;
    const int strideY = Dsz * C_CH;

    const float z1 = bz1 * scale, y1 = by1 * scale, x1 = bx1 * scale;
    const float binz = fmaxf(bz2 * scale - z1, 1.0f) * (1.0f / 7.0f);
    const float biny = fmaxf(by2 * scale - y1, 1.0f) * (1.0f / 7.0f);
    const float binx = fmaxf(bx2 * scale - x1, 1.0f) * (1.0f / 7.0f);

    const int tid = threadIdx.x;

    // ---- per-ROI tap tables with duplicate merge (21 threads, once) ----
    if (tid < 21) {
        const int dim = tid / 7;
        const int o   = tid - dim * 7;
        const float start  = (dim == 0) ? z1 : (dim == 1) ? y1 : x1;
        const float bin    = (dim == 0) ? binz : (dim == 1) ? biny : binx;
        const int   stride = (dim == 0) ? strideZ : (dim == 1) ? strideY : C_CH;

        int to[4]; float tw[4];
        dim_taps(start, bin, o, Dsz, stride, to, tw);

        int n = 0; int uo[4]; float uw[4];
#pragma unroll
        for (int t = 0; t < 4; t++) {
            if (tw[t] != 0.0f) {
                bool found = false;
#pragma unroll
                for (int j = 0; j < 4; j++) {
                    if (j < n && uo[j] == to[t]) { uw[j] += tw[t]; found = true; }
                }
                if (!found) { uo[n] = to[t]; uw[n] = tw[t]; n++; }
            }
        }
        s_cnt[dim][o] = n;
#pragma unroll
        for (int j = 0; j < 4; j++) {
            if (j < n) { s_off[dim][o][j] = uo[j]; s_wt[dim][o][j] = uw[j]; }
        }
    }
    __syncthreads();

    const int lane = tid & 31;
    const int warp = tid >> 5;       // 0..23
    const int h = lane >> 4;         // cell half
    const int q = lane & 15;         // channel quad

    const float* base = ft + (size_t)b * DHW * C_CH + 4 * q;

    for (int cb = 2 * warp; cb < CELLS; cb += 48) {
        const int cell = cb + h;
        const int cc   = min(cell, CELLS - 1);
        const int oz   = cc / 49;
        const int rem  = cc - oz * 49;
        const int oy   = rem / 7;
        const int ox   = rem - oy * 7;

        const int nz = s_cnt[0][oz];
        const int ny = s_cnt[1][oy];
        const int nx = s_cnt[2][ox];

        float a0 = 0.f, a1 = 0.f, a2 = 0.f, a3 = 0.f;
        for (int i = 0; i < nz; i++) {
            const float wz = s_wt[0][oz][i];
            const int   zo = s_off[0][oz][i];
            for (int j = 0; j < ny; j++) {
                const float wzy = wz * s_wt[1][oy][j];
                const int   ozy = zo + s_off[1][oy][j];
                for (int k = 0; k < nx; k++) {
                    const float w  = wzy * s_wt[2][ox][k];
                    const float4 v = *(const float4*)(base + ozy + s_off[2][ox][k]);
                    a0 = fmaf(w, v.x, a0);
                    a1 = fmaf(w, v.y, a1);
                    a2 = fmaf(w, v.z, a2);
                    a3 = fmaf(w, v.w, a3);
                }
            }
        }

        if (cell < CELLS) {
            s_out[(4 * q + 0) * CELLS + cell] = a0;
            s_out[(4 * q + 1) * CELLS + cell] = a1;
            s_out[(4 * q + 2) * CELLS + cell] = a2;
            s_out[(4 * q + 3) * CELLS + cell] = a3;
        }
    }

    __syncthreads();

    float4*       o4 = (float4*)(out + (size_t)r * OUT_PER_ROI);
    const float4* s4 = (const float4*)s_out;
    for (int i = tid; i < OUT_PER_ROI / 4; i += 768)
        o4[i] = s4[i];
}

// ---------------------------------------------------------------------------
extern "C" void kernel_launch(void* const* d_in, const int* in_sizes, int n_in,
                              void* d_out, int out_size) {
    const float* x0    = (const float*)d_in[0];
    const float* x1    = (const float*)d_in[1];
    const float* x2    = (const float*)d_in[2];
    const float* x3    = (const float*)d_in[3];
    const float* boxes = (const float*)d_in[4];

    cudaFuncSetAttribute(roi_align_kernel,
                         cudaFuncAttributeMaxDynamicSharedMemorySize,
                         OUT_PER_ROI * (int)sizeof(float));

    transpose_all_kernel<<<2288, dim3(32, 32)>>>(x0, x1, x2, x3);

    roi_align_kernel<<<NROI, 768, OUT_PER_ROI * (int)sizeof(float)>>>(
        boxes, (float*)d_out);
}

// round 4
// speedup vs baseline: 2.6881x; 1.2692x over previous
#include <cuda_runtime.h>
#include <cuda_bf16.h>
#include <cstdint>

// ---------------------------------------------------------------------------
// ROIAlignPooler (3D, 4-level FPN) for B200 (sm_100a)
//
//   1. Fused transpose: all 4 levels NCDHW -> N DHW C (channel-last scratch),
//      float4 global loads where DHW % 4 == 0.
//   2. Main kernel: one block per ROI (256 blocks, 768 thr, single wave).
//      Per-ROI: per-dim merged tap tables (dup coords merged, zero-weight
//      pruned), then y*x tables fused into 49 flat (offset, wy*wx) lists.
//      Per cell: loop z (<=4) x loop yx (typ 4): LDS.64 + LDG.128 + 4 FMA.
//   3. Warp handles 2 cells: lane = (cell half, channel quad), float4/lane.
//   4. Output staged in shared [C][343], float4 coalesced writeout.
// ---------------------------------------------------------------------------

#define NROI    256
#define C_CH    64
#define CELLS   343
#define OUT_PER_ROI (C_CH * CELLS)   // 21952

__device__ __align__(16) float g_t0[2 * 40 * 40 * 40 * C_CH];
__device__ __align__(16) float g_t1[2 * 20 * 20 * 20 * C_CH];
__device__ __align__(16) float g_t2[2 * 10 * 10 * 10 * C_CH];
__device__ __align__(16) float g_t3[2 * 5 * 5 * 5 * C_CH];

// ---------------------------------------------------------------------------
// Fused transpose: src[b][c][sp] -> dst[b][sp][c], all levels in one launch.
// ---------------------------------------------------------------------------
__global__ __launch_bounds__(1024)
void transpose_all_kernel(const float* __restrict__ x0,
                          const float* __restrict__ x1,
                          const float* __restrict__ x2,
                          const float* __restrict__ x3) {
    __shared__ float tile[32][133];

    const int bx = blockIdx.x;
    const float* src; float* dst; int DHW, spTiles, t0;
    if (bx < 2000)      { src = x0; dst = g_t0; DHW = 64000; spTiles = 500; t0 = bx; }
    else if (bx < 2252) { src = x1; dst = g_t1; DHW = 8000;  spTiles = 63;  t0 = bx - 2000; }
    else if (bx < 2284) { src = x2; dst = g_t2; DHW = 1000;  spTiles = 8;   t0 = bx - 2252; }
    else                { src = x3; dst = g_t3; DHW = 125;   spTiles = 1;   t0 = bx - 2284; }

    const int st = t0 % spTiles;
    const int t1 = t0 / spTiles;
    const int cg = t1 & 1;
    const int b  = t1 >> 1;
    const int cBase = cg * 32;
    const int sBase = st * 128;
    const int tx = threadIdx.x, ty = threadIdx.y;

    if ((DHW & 3) == 0) {
        // float4 load path (levels 0..2): thread covers sp4 = sBase + 4*tx
        int sp4 = sBase + 4 * tx;
        if (sp4 < DHW) {
            const float4 v = *(const float4*)(
                src + (size_t)(b * C_CH + cBase + ty) * DHW + sp4);
            tile[ty][4 * tx + 0] = v.x;
            tile[ty][4 * tx + 1] = v.y;
            tile[ty][4 * tx + 2] = v.z;
            tile[ty][4 * tx + 3] = v.w;
        }
    } else {
#pragma unroll
        for (int k = 0; k < 4; k++) {
            int sp = sBase + 32 * k + tx;
            if (sp < DHW)
                tile[ty][32 * k + tx] =
                    src[(size_t)(b * C_CH + cBase + ty) * DHW + sp];
        }
    }
    __syncthreads();
#pragma unroll
    for (int k = 0; k < 4; k++) {
        int sp = sBase + 32 * k + ty;
        if (sp < DHW)
            dst[((size_t)b * DHW + sp) * C_CH + cBase + tx] = tile[tx][32 * k + ty];
    }
}

// ---------------------------------------------------------------------------
// Per-dim taps: 2 supersamples x 2 corners. Weight includes the 0.5 per-dim
// averaging factor; offsets pre-scaled by the dim's element stride.
// ---------------------------------------------------------------------------
__device__ __forceinline__ void dim_taps(float start, float bin, int o, int Dsz,
                                         int stride, int* to, float* tw) {
#pragma unroll
    for (int r = 0; r < 2; r++) {
        float c = start + ((float)(2 * o + r) + 0.5f) * 0.5f * bin;
        float valid = (c > -1.0f && c < (float)Dsz) ? 0.5f : 0.0f;
        c = fminf(fmaxf(c, 0.0f), (float)Dsz - 1.0f);
        float low = floorf(c);
        int li = (int)low;
        int hi = min(li + 1, Dsz - 1);
        float f = c - low;
        to[2 * r]     = li * stride;
        tw[2 * r]     = (1.0f - f) * valid;
        to[2 * r + 1] = hi * stride;
        tw[2 * r + 1] = f * valid;
    }
}

// ---------------------------------------------------------------------------
// Main kernel: one block per ROI, 768 threads = 24 warps, 2 blocks/SM.
// ---------------------------------------------------------------------------
extern __shared__ float s_out[];   // [C_CH][CELLS] = 87808 bytes (dynamic)

__global__ __launch_bounds__(768, 2)
void roi_align_kernel(const float* __restrict__ boxes, float* __restrict__ out) {
    __shared__ int    s_cnt[3][7];        // merged counts per dim/bin
    __shared__ int    s_off[3][7][4];
    __shared__ float  s_wt [3][7][4];
    __shared__ int    s_nyx[49];          // fused y*x list length
    __shared__ float2 s_yx[49][16];       // (.x = offset bits, .y = wy*wx)

    const int r = blockIdx.x;
    const int b = r >> 7;            // nb = 128

    const float bz1 = boxes[r * 6 + 0];
    const float by1 = boxes[r * 6 + 1];
    const float bx1 = boxes[r * 6 + 2];
    const float bz2 = boxes[r * 6 + 3];
    const float by2 = boxes[r * 6 + 4];
    const float bx2 = boxes[r * 6 + 5];

    const float area = (bz2 - bz1 + 1.0f) * (by2 - by1 + 1.0f) * (bx2 - bx1 + 1.0f);
    const float s    = sqrtf(area);
    float lf = floorf(4.0f + log2f(s / 224.0f + 1e-6f));
    lf = fminf(fmaxf(lf, 2.0f), 5.0f);
    const int lvl = (int)lf - 2;

    const float* ft; int Dsz; float scale;
    if (lvl == 0)      { ft = g_t0; Dsz = 40; scale = 0.25f;    }
    else if (lvl == 1) { ft = g_t1; Dsz = 20; scale = 0.125f;   }
    else if (lvl == 2) { ft = g_t2; Dsz = 10; scale = 0.0625f;  }
    else               { ft = g_t3; Dsz = 5;  scale = 0.03125f; }

    const int DHW     = Dsz * Dsz * Dsz;
    const int strideZ = Dsz * Dsz * C_CH;
    const int strideY = Dsz * C_CH;

    const float z1 = bz1 * scale, y1 = by1 * scale, x1 = bx1 * scale;
    const float binz = fmaxf(bz2 * scale - z1, 1.0f) * (1.0f / 7.0f);
    const float biny = fmaxf(by2 * scale - y1, 1.0f) * (1.0f / 7.0f);
    const float binx = fmaxf(bx2 * scale - x1, 1.0f) * (1.0f / 7.0f);

    const int tid = threadIdx.x;

    // ---- phase 1: per-dim merged tap tables (21 threads) ----
    if (tid < 21) {
        const int dim = tid / 7;
        const int o   = tid - dim * 7;
        const float start  = (dim == 0) ? z1 : (dim == 1) ? y1 : x1;
        const float bin    = (dim == 0) ? binz : (dim == 1) ? biny : binx;
        const int   stride = (dim == 0) ? strideZ : (dim == 1) ? strideY : C_CH;

        int to[4]; float tw[4];
        dim_taps(start, bin, o, Dsz, stride, to, tw);

        int n = 0; int uo[4]; float uw[4];
#pragma unroll
        for (int t = 0; t < 4; t++) {
            if (tw[t] != 0.0f) {
                bool found = false;
#pragma unroll
                for (int j = 0; j < 4; j++) {
                    if (j < n && uo[j] == to[t]) { uw[j] += tw[t]; found = true; }
                }
                if (!found) { uo[n] = to[t]; uw[n] = tw[t]; n++; }
            }
        }
        s_cnt[dim][o] = n;
#pragma unroll
        for (int j = 0; j < 4; j++) {
            if (j < n) { s_off[dim][o][j] = uo[j]; s_wt[dim][o][j] = uw[j]; }
        }
    }
    __syncthreads();

    // ---- phase 2: fuse y*x tables into 49 flat lists (49 threads) ----
    if (tid < 49) {
        const int oy = tid / 7;
        const int ox = tid - oy * 7;
        const int ny = s_cnt[1][oy];
        const int nx = s_cnt[2][ox];
        int m = 0;
        for (int j = 0; j < ny; j++) {
            const int   yo = s_off[1][oy][j];
            const float wy = s_wt[1][oy][j];
            for (int k = 0; k < nx; k++) {
                s_yx[tid][m] = make_float2(
                    __int_as_float(yo + s_off[2][ox][k]),
                    wy * s_wt[2][ox][k]);
                m++;
            }
        }
        s_nyx[tid] = m;
    }
    __syncthreads();

    const int lane = tid & 31;
    const int warp = tid >> 5;       // 0..23
    const int h = lane >> 4;         // cell half
    const int q = lane & 15;         // channel quad

    const float* base = ft + (size_t)b * DHW * C_CH + 4 * q;

    for (int cb = 2 * warp; cb < CELLS; cb += 48) {
        const int cell = cb + h;
        const int cc   = min(cell, CELLS - 1);
        const int oz   = cc / 49;
        const int rem  = cc - oz * 49;

        const int nz  = s_cnt[0][oz];
        const int nyx = s_nyx[rem];
        const float2* lst = s_yx[rem];

        float a0 = 0.f, a1 = 0.f, a2 = 0.f, a3 = 0.f;
        for (int i = 0; i < nz; i++) {
            const float wz = s_wt[0][oz][i];
            const int   zo = s_off[0][oz][i];
            for (int t = 0; t < nyx; t++) {
                const float2 e = lst[t];
                const float  w = wz * e.y;
                const float4 v = *(const float4*)(base + zo + __float_as_int(e.x));
                a0 = fmaf(w, v.x, a0);
                a1 = fmaf(w, v.y, a1);
                a2 = fmaf(w, v.z, a2);
                a3 = fmaf(w, v.w, a3);
            }
        }

        if (cell < CELLS) {
            s_out[(4 * q + 0) * CELLS + cell] = a0;
            s_out[(4 * q + 1) * CELLS + cell] = a1;
            s_out[(4 * q + 2) * CELLS + cell] = a2;
            s_out[(4 * q + 3) * CELLS + cell] = a3;
        }
    }

    __syncthreads();

    float4*       o4 = (float4*)(out + (size_t)r * OUT_PER_ROI);
    const float4* s4 = (const float4*)s_out;
    for (int i = tid; i < OUT_PER_ROI / 4; i += 768)
        o4[i] = s4[i];
}

// ---------------------------------------------------------------------------
extern "C" void kernel_launch(void* const* d_in, const int* in_sizes, int n_in,
                              void* d_out, int out_size) {
    const float* x0    = (const float*)d_in[0];
    const float* x1    = (const float*)d_in[1];
    const float* x2    = (const float*)d_in[2];
    const float* x3    = (const float*)d_in[3];
    const float* boxes = (const float*)d_in[4];

    cudaFuncSetAttribute(roi_align_kernel,
                         cudaFuncAttributeMaxDynamicSharedMemorySize,
                         OUT_PER_ROI * (int)sizeof(float));

    transpose_all_kernel<<<2288, dim3(32, 32)>>>(x0, x1, x2, x3);

    roi_align_kernel<<<NROI, 768, OUT_PER_ROI * (int)sizeof(float)>>>(
        boxes, (float*)d_out);
}